// round 2
// baseline (speedup 1.0000x reference)
#include <cuda_runtime.h>
#include <math.h>

#define NN    100000
#define EE    3200000
#define ET    (EE + NN)
#define HIDC  256
#define NHEAD 8
#define OUTC  40

// ---------------- scratch (static __device__, no allocations) ----------------
__device__ __align__(128) float g_lin  [(size_t)NN * HIDC];
__device__ __align__(128) float g_feat0[(size_t)NN * HIDC];
__device__ __align__(128) float g_feat1[(size_t)NN * HIDC];
__device__ __align__(128) float g_feat2[(size_t)NN * HIDC];
__device__ __align__(128) float g_esrc [NN * NHEAD];
__device__ __align__(128) float g_edst [NN * NHEAD];
__device__ __align__(128) float g_inv  [NN * NHEAD];
__device__ __align__(128) float g_alpha[(size_t)ET * NHEAD];
__device__ __align__(128) int   g_cnt   [NN];
__device__ __align__(128) int   g_rowptr[NN + 1];
__device__ __align__(128) int   g_cursor[NN];
__device__ __align__(128) int   g_csrsrc[ET];
__device__ int g_odd_nonzero;  // 0 -> edge_index is int64; nonzero -> int32

// ---------------- CSR build ----------------
__global__ void k_zero() {
    int i = blockIdx.x * blockDim.x + threadIdx.x;
    if (i < NN) g_cnt[i] = 0;
    if (i == 0) g_odd_nonzero = 0;
}

// Detect edge_index dtype: if int64, every odd 32-bit word (high half of values
// < 100000) is zero. If int32, odd words are random node ids, almost surely nonzero.
__global__ void k_detect(const int* __restrict__ ei32) {
    int i = blockIdx.x * blockDim.x + threadIdx.x;
    if (i < 4096) {
        if (ei32[2 * i + 1] != 0) atomicOr(&g_odd_nonzero, 1);
    }
}

__global__ void k_hist(const void* __restrict__ ei) {
    int e = blockIdx.x * blockDim.x + threadIdx.x;
    if (e >= ET) return;
    int dst;
    if (e >= EE) {
        dst = e - EE;                                  // self loop
    } else if (g_odd_nonzero == 0) {
        dst = (int)((const long long*)ei)[(size_t)EE + e];
    } else {
        dst = ((const int*)ei)[(size_t)EE + e];
    }
    atomicAdd(&g_cnt[dst], 1);
}

__global__ void k_scan() {   // single block, 1024 threads, exclusive scan of g_cnt
    __shared__ int sums[1024];
    const int t = threadIdx.x;
    const int CH = (NN + 1023) / 1024;  // 98
    const int b0 = t * CH;
    int local = 0;
    for (int j = 0; j < CH; j++) {
        int idx = b0 + j;
        if (idx < NN) local += g_cnt[idx];
    }
    sums[t] = local;
    __syncthreads();
    for (int off = 1; off < 1024; off <<= 1) {
        int u = (t >= off) ? sums[t - off] : 0;
        __syncthreads();
        sums[t] += u;
        __syncthreads();
    }
    int run = (t == 0) ? 0 : sums[t - 1];
    for (int j = 0; j < CH; j++) {
        int idx = b0 + j;
        if (idx < NN) {
            g_rowptr[idx] = run;
            g_cursor[idx] = run;
            run += g_cnt[idx];
        }
    }
    if (t == 1023) g_rowptr[NN] = sums[1023];
}

__global__ void k_scatter(const void* __restrict__ ei) {
    int e = blockIdx.x * blockDim.x + threadIdx.x;
    if (e >= ET) return;
    int src, dst;
    if (e >= EE) {
        src = e - EE; dst = src;
    } else if (g_odd_nonzero == 0) {
        const long long* p = (const long long*)ei;
        src = (int)p[e]; dst = (int)p[(size_t)EE + e];
    } else {
        const int* p = (const int*)ei;
        src = p[e]; dst = p[(size_t)EE + e];
    }
    int pos = atomicAdd(&g_cursor[dst], 1);
    g_csrsrc[pos] = src;
}

// ---------------- SGEMM: C[M,Nc] = A[M,K] @ B[K,Nc]  (fp32, 128x128x4, dbuf) ----
__global__ __launch_bounds__(256) void k_sgemm(
    const float* __restrict__ A, const float* __restrict__ Bw,
    float* __restrict__ C, int M, int K, int Nc)
{
    __shared__ __align__(16) float As[2][4][128];
    __shared__ __align__(16) float Bs[2][4][128];
    const int tid = threadIdx.x;
    const int tx = tid & 15, ty = tid >> 4;
    const int bm = blockIdx.y * 128, bn = blockIdx.x * 128;
    const int aRow = bm + tid;               // valid when tid < 128
    const int bRow = (tid - 128) >> 5;       // valid when tid >= 128
    const int bCol = ((tid - 128) & 31) * 4;

    float acc[8][8];
#pragma unroll
    for (int i = 0; i < 8; i++)
#pragma unroll
        for (int j = 0; j < 8; j++) acc[i][j] = 0.f;

    float4 v;
    if (tid < 128) {
        v = (aRow < M) ? *(const float4*)(A + (size_t)aRow * K)
                       : make_float4(0.f, 0.f, 0.f, 0.f);
        As[0][0][tid] = v.x; As[0][1][tid] = v.y; As[0][2][tid] = v.z; As[0][3][tid] = v.w;
    } else {
        v = *(const float4*)(Bw + (size_t)bRow * Nc + bn + bCol);
        *(float4*)&Bs[0][bRow][bCol] = v;
    }
    __syncthreads();

    const int kTiles = K >> 2;
    int buf = 0;
    for (int t = 1; t < kTiles; t++) {
        const int k0 = t * 4;
        if (tid < 128) {
            v = (aRow < M) ? *(const float4*)(A + (size_t)aRow * K + k0)
                           : make_float4(0.f, 0.f, 0.f, 0.f);
        } else {
            v = *(const float4*)(Bw + (size_t)(k0 + bRow) * Nc + bn + bCol);
        }
#pragma unroll
        for (int kk = 0; kk < 4; kk++) {
            float a[8], b[8];
            *(float4*)&a[0] = *(const float4*)&As[buf][kk][ty * 8];
            *(float4*)&a[4] = *(const float4*)&As[buf][kk][ty * 8 + 4];
            *(float4*)&b[0] = *(const float4*)&Bs[buf][kk][tx * 8];
            *(float4*)&b[4] = *(const float4*)&Bs[buf][kk][tx * 8 + 4];
#pragma unroll
            for (int i = 0; i < 8; i++)
#pragma unroll
                for (int j = 0; j < 8; j++) acc[i][j] = fmaf(a[i], b[j], acc[i][j]);
        }
        const int nb = buf ^ 1;
        if (tid < 128) {
            As[nb][0][tid] = v.x; As[nb][1][tid] = v.y; As[nb][2][tid] = v.z; As[nb][3][tid] = v.w;
        } else {
            *(float4*)&Bs[nb][bRow][bCol] = v;
        }
        __syncthreads();
        buf = nb;
    }
#pragma unroll
    for (int kk = 0; kk < 4; kk++) {
        float a[8], b[8];
        *(float4*)&a[0] = *(const float4*)&As[buf][kk][ty * 8];
        *(float4*)&a[4] = *(const float4*)&As[buf][kk][ty * 8 + 4];
        *(float4*)&b[0] = *(const float4*)&Bs[buf][kk][tx * 8];
        *(float4*)&b[4] = *(const float4*)&Bs[buf][kk][tx * 8 + 4];
#pragma unroll
        for (int i = 0; i < 8; i++)
#pragma unroll
            for (int j = 0; j < 8; j++) acc[i][j] = fmaf(a[i], b[j], acc[i][j]);
    }

#pragma unroll
    for (int i = 0; i < 8; i++) {
        int m = bm + ty * 8 + i;
        if (m < M) {
            float* cp = C + (size_t)m * Nc + bn + tx * 8;
            *(float4*)cp       = make_float4(acc[i][0], acc[i][1], acc[i][2], acc[i][3]);
            *(float4*)(cp + 4) = make_float4(acc[i][4], acc[i][5], acc[i][6], acc[i][7]);
        }
    }
}

// ---------------- per-node attention logits: e_src/e_dst ----------------
__global__ void k_att(const float* __restrict__ asrc, const float* __restrict__ adst) {
    const int n = blockIdx.x;
    const int c = threadIdx.x;
    const int lane = c & 31, head = c >> 5;
    float hv = g_lin[(size_t)n * HIDC + c];
    float vs = hv * asrc[c];
    float vd = hv * adst[c];
#pragma unroll
    for (int o = 16; o; o >>= 1) {
        vs += __shfl_xor_sync(0xffffffffu, vs, o);
        vd += __shfl_xor_sync(0xffffffffu, vd, o);
    }
    if (lane == 0) {
        g_esrc[n * NHEAD + head] = vs;
        g_edst[n * NHEAD + head] = vd;
    }
}

// ---------------- segment softmax (warp per dst node, no atomics) ----------------
__global__ void k_soft() {
    const int n = (blockIdx.x * blockDim.x + threadIdx.x) >> 5;
    const int lane = threadIdx.x & 31;
    if (n >= NN) return;
    const int beg = g_rowptr[n], end = g_rowptr[n + 1];
    float ed[8];
    *(float4*)&ed[0] = *(const float4*)&g_edst[n * 8];
    *(float4*)&ed[4] = *(const float4*)&g_edst[n * 8 + 4];
    float mx[8];
#pragma unroll
    for (int h = 0; h < 8; h++) mx[h] = -1e30f;
    for (int i = beg + lane; i < end; i += 32) {
        int s = g_csrsrc[i];
        float es[8];
        *(float4*)&es[0] = *(const float4*)&g_esrc[s * 8];
        *(float4*)&es[4] = *(const float4*)&g_esrc[s * 8 + 4];
#pragma unroll
        for (int h = 0; h < 8; h++) {
            float t = es[h] + ed[h];
            t = (t > 0.f) ? t : 0.2f * t;
            mx[h] = fmaxf(mx[h], t);
        }
    }
#pragma unroll
    for (int h = 0; h < 8; h++)
#pragma unroll
        for (int o = 16; o; o >>= 1) mx[h] = fmaxf(mx[h], __shfl_xor_sync(0xffffffffu, mx[h], o));

    float sm[8];
#pragma unroll
    for (int h = 0; h < 8; h++) sm[h] = 0.f;
    for (int i = beg + lane; i < end; i += 32) {
        int s = g_csrsrc[i];
        float es[8];
        *(float4*)&es[0] = *(const float4*)&g_esrc[s * 8];
        *(float4*)&es[4] = *(const float4*)&g_esrc[s * 8 + 4];
        float w[8];
#pragma unroll
        for (int h = 0; h < 8; h++) {
            float t = es[h] + ed[h];
            t = (t > 0.f) ? t : 0.2f * t;
            w[h] = expf(t - mx[h]);
            sm[h] += w[h];
        }
        *(float4*)&g_alpha[(size_t)i * 8]     = make_float4(w[0], w[1], w[2], w[3]);
        *(float4*)&g_alpha[(size_t)i * 8 + 4] = make_float4(w[4], w[5], w[6], w[7]);
    }
#pragma unroll
    for (int h = 0; h < 8; h++)
#pragma unroll
        for (int o = 16; o; o >>= 1) sm[h] += __shfl_xor_sync(0xffffffffu, sm[h], o);
    if (lane == 0) {
#pragma unroll
        for (int h = 0; h < 8; h++) g_inv[n * 8 + h] = 1.0f / (sm[h] + 1e-16f);
    }
}

// ---------------- message aggregation (warp per dst node) ----------------
__global__ void k_agg(const float* __restrict__ bias, float* __restrict__ outf, int do_elu) {
    const int n = (blockIdx.x * blockDim.x + threadIdx.x) >> 5;
    const int lane = threadIdx.x & 31;
    if (n >= NN) return;
    const int beg = g_rowptr[n], end = g_rowptr[n + 1];
    const int h = lane >> 2;                 // head of this lane's 8 channels
    float acc[8];
#pragma unroll
    for (int j = 0; j < 8; j++) acc[j] = 0.f;

    int s = (beg < end) ? g_csrsrc[beg] : 0;
    for (int i = beg; i < end; i++) {
        int sn = (i + 1 < end) ? g_csrsrc[i + 1] : 0;
        float a = g_alpha[(size_t)i * 8 + h];
        const float4* hp = (const float4*)(g_lin + (size_t)s * HIDC + lane * 8);
        float4 v0 = hp[0], v1 = hp[1];
        acc[0] = fmaf(a, v0.x, acc[0]); acc[1] = fmaf(a, v0.y, acc[1]);
        acc[2] = fmaf(a, v0.z, acc[2]); acc[3] = fmaf(a, v0.w, acc[3]);
        acc[4] = fmaf(a, v1.x, acc[4]); acc[5] = fmaf(a, v1.y, acc[5]);
        acc[6] = fmaf(a, v1.z, acc[6]); acc[7] = fmaf(a, v1.w, acc[7]);
        s = sn;
    }
    const float inv = g_inv[n * 8 + h];
    const int c0 = lane * 8;
    float o[8];
#pragma unroll
    for (int j = 0; j < 8; j++) {
        float v = acc[j] * inv + bias[c0 + j];
        if (do_elu) v = (v > 0.f) ? v : expm1f(v);
        o[j] = v;
    }
    float4* op = (float4*)(outf + (size_t)n * HIDC + c0);
    op[0] = make_float4(o[0], o[1], o[2], o[3]);
    op[1] = make_float4(o[4], o[5], o[6], o[7]);
}

// ---------------- fused JK-max + final linear + log_softmax ----------------
__global__ __launch_bounds__(160) void k_final(
    const float* __restrict__ Wf, const float* __restrict__ bf, float* __restrict__ out)
{
    __shared__ __align__(16) float sW[HIDC * OUTC];
    __shared__ float sb[OUTC];
    __shared__ __align__(16) float sl[32][OUTC];
    const int t = threadIdx.x;
    for (int i = t; i < HIDC * OUTC; i += 160) sW[i] = Wf[i];
    if (t < OUTC) sb[t] = bf[t];
    __syncthreads();

    const int r = t / 5;              // row within block (0..31)
    const int og = (t % 5) * 8;       // output group (0,8,16,24,32)
    const int node = blockIdx.x * 32 + r;
    float acc[8];
#pragma unroll
    for (int j = 0; j < 8; j++) acc[j] = 0.f;
    const float* p0 = g_feat0 + (size_t)node * HIDC;
    const float* p1 = g_feat1 + (size_t)node * HIDC;
    const float* p2 = g_feat2 + (size_t)node * HIDC;
    for (int k = 0; k < HIDC; k++) {
        float v = fmaxf(fmaxf(p0[k], p1[k]), p2[k]);
        const float4* wp = (const float4*)&sW[k * OUTC + og];
        float4 w0 = wp[0], w1 = wp[1];
        acc[0] = fmaf(v, w0.x, acc[0]); acc[1] = fmaf(v, w0.y, acc[1]);
        acc[2] = fmaf(v, w0.z, acc[2]); acc[3] = fmaf(v, w0.w, acc[3]);
        acc[4] = fmaf(v, w1.x, acc[4]); acc[5] = fmaf(v, w1.y, acc[5]);
        acc[6] = fmaf(v, w1.z, acc[6]); acc[7] = fmaf(v, w1.w, acc[7]);
    }
#pragma unroll
    for (int j = 0; j < 8; j++) acc[j] += sb[og + j];
    *(float4*)&sl[r][og]     = make_float4(acc[0], acc[1], acc[2], acc[3]);
    *(float4*)&sl[r][og + 4] = make_float4(acc[4], acc[5], acc[6], acc[7]);
    __syncthreads();

    if (t < 32) {
        const int nd = blockIdx.x * 32 + t;
        float m = -1e30f;
        for (int o = 0; o < OUTC; o++) m = fmaxf(m, sl[t][o]);
        float ssum = 0.f;
        for (int o = 0; o < OUTC; o++) ssum += expf(sl[t][o] - m);
        const float lse = m + logf(ssum);
        for (int o = 0; o < OUTC; o++) out[(size_t)nd * OUTC + o] = sl[t][o] - lse;
    }
}

// ---------------- launch ----------------
extern "C" void kernel_launch(void* const* d_in, const int* in_sizes, int n_in,
                              void* d_out, int out_size)
{
    (void)in_sizes; (void)n_in; (void)out_size;
    const float* x  = (const float*)d_in[0];
    const void*  ei = d_in[1];
    const float* W[3]  = {(const float*)d_in[2], (const float*)d_in[6],  (const float*)d_in[10]};
    const float* As[3] = {(const float*)d_in[3], (const float*)d_in[7],  (const float*)d_in[11]};
    const float* Ad[3] = {(const float*)d_in[4], (const float*)d_in[8],  (const float*)d_in[12]};
    const float* Bb[3] = {(const float*)d_in[5], (const float*)d_in[9],  (const float*)d_in[13]};
    const float* Wf = (const float*)d_in[14];
    const float* bf = (const float*)d_in[15];
    float* out = (float*)d_out;

    float *lin, *f0, *f1, *f2;
    cudaGetSymbolAddress((void**)&lin, g_lin);
    cudaGetSymbolAddress((void**)&f0, g_feat0);
    cudaGetSymbolAddress((void**)&f1, g_feat1);
    cudaGetSymbolAddress((void**)&f2, g_feat2);

    k_zero<<<(NN + 255) / 256, 256>>>();
    k_detect<<<16, 256>>>((const int*)ei);
    k_hist<<<(ET + 255) / 256, 256>>>(ei);
    k_scan<<<1, 1024>>>();
    k_scatter<<<(ET + 255) / 256, 256>>>(ei);

    float* feats[3] = {f0, f1, f2};
    const float* ins[3] = {x, f0, f1};
    const int Ks[3] = {500, 256, 256};
    for (int l = 0; l < 3; l++) {
        dim3 grid(HIDC / 128, (NN + 127) / 128);
        k_sgemm<<<grid, 256>>>(ins[l], W[l], lin, NN, Ks[l], HIDC);
        k_att<<<NN, 256>>>(As[l], Ad[l]);
        k_soft<<<(NN + 7) / 8, 256>>>();
        k_agg<<<(NN + 7) / 8, 256>>>(Bb[l], feats[l], (l < 2) ? 1 : 0);
    }
    k_final<<<NN / 32, 160>>>(Wf, bf, out);
}